// round 7
// baseline (speedup 1.0000x reference)
#include <cuda_runtime.h>
#include <cuda_fp16.h>

#define D 128
#define NMAX 100000
#define PAD 20

__device__ __half g_h[2][(size_t)NMAX * D];
__device__ int g_idx64;

__device__ __forceinline__ unsigned f2tf32(float f) {
    unsigned u;
    asm("cvt.rna.tf32.f32 %0, %1;" : "=r"(u) : "f"(f));
    return u;
}

__device__ __forceinline__ void mma_tf32(float c[4], unsigned a0, unsigned a1,
                                         unsigned a2, unsigned a3,
                                         unsigned b0, unsigned b1) {
    asm volatile(
        "mma.sync.aligned.m16n8k8.row.col.f32.tf32.tf32.f32 "
        "{%0,%1,%2,%3},{%4,%5,%6,%7},{%8,%9},{%0,%1,%2,%3};"
        : "+f"(c[0]), "+f"(c[1]), "+f"(c[2]), "+f"(c[3])
        : "r"(a0), "r"(a1), "r"(a2), "r"(a3), "r"(b0), "r"(b1));
}

// ---------------------------------------------------------------------------
// Fused node GEMM: one pass over x computes BOTH h_src and h_dst.
// Also performs index-dtype detection (block 0) to kill the extra launch.
// ---------------------------------------------------------------------------
__global__ __launch_bounds__(512, 1) void node_gemm_fused(
    const float* __restrict__ x,
    const float* __restrict__ Wsrc, const float* __restrict__ bsrc,
    const float* __restrict__ Wdst, const float* __restrict__ bdst,
    const long long* __restrict__ idxprobe, int N)
{
    __shared__ unsigned As[128][PAD];
    __shared__ unsigned Bs[2][128][PAD];

    const int tid  = threadIdx.x;

    if (blockIdx.x == 0 && tid == 0) {
        int ok = 0;
#pragma unroll
        for (int i = 0; i < 16; i++) {
            long long v = idxprobe[i];
            if (v >= 0 && v < (long long)N) ok++;
        }
        g_idx64 = (ok >= 12) ? 1 : 0;
    }

    const int wid  = tid >> 5;
    const int lane = tid & 31;
    const int half = wid >> 3;            // 0 = src, 1 = dst
    const int w    = wid & 7;
    const int wm   = (w >> 2) * 64;
    const int wn   = (w & 3) * 32;
    const int row0 = blockIdx.x * 128;
    const int tg   = lane >> 2;
    const int tr   = lane & 3;

    const float* __restrict__ bh = half ? bdst : bsrc;
    __half* __restrict__ out = g_h[half];

    float acc[4][4][4];
#pragma unroll
    for (int i = 0; i < 4; i++)
#pragma unroll
        for (int j = 0; j < 4; j++)
#pragma unroll
            for (int k = 0; k < 4; k++) acc[i][j][k] = 0.0f;

    const int lrow  = tid >> 2;
    const int lcol4 = (tid & 3) * 4;

    for (int kt = 0; kt < 128; kt += 16) {
        float4 av = make_float4(0.f, 0.f, 0.f, 0.f);
        if (row0 + lrow < N)
            av = *(const float4*)(x + (size_t)(row0 + lrow) * D + kt + lcol4);
        As[lrow][lcol4+0] = f2tf32(av.x); As[lrow][lcol4+1] = f2tf32(av.y);
        As[lrow][lcol4+2] = f2tf32(av.z); As[lrow][lcol4+3] = f2tf32(av.w);

        const float4 ws = *(const float4*)(Wsrc + (size_t)lrow * D + kt + lcol4);
        Bs[0][lrow][lcol4+0] = f2tf32(ws.x); Bs[0][lrow][lcol4+1] = f2tf32(ws.y);
        Bs[0][lrow][lcol4+2] = f2tf32(ws.z); Bs[0][lrow][lcol4+3] = f2tf32(ws.w);

        const float4 wd = *(const float4*)(Wdst + (size_t)lrow * D + kt + lcol4);
        Bs[1][lrow][lcol4+0] = f2tf32(wd.x); Bs[1][lrow][lcol4+1] = f2tf32(wd.y);
        Bs[1][lrow][lcol4+2] = f2tf32(wd.z); Bs[1][lrow][lcol4+3] = f2tf32(wd.w);
        __syncthreads();

#pragma unroll
        for (int kk = 0; kk < 16; kk += 8) {
            unsigned bf[4][2];
#pragma unroll
            for (int nt = 0; nt < 4; nt++) {
                bf[nt][0] = Bs[half][wn + nt*8 + tg][kk + tr];
                bf[nt][1] = Bs[half][wn + nt*8 + tg][kk + tr + 4];
            }
#pragma unroll
            for (int mt = 0; mt < 4; mt++) {
                const int ar = wm + mt*16 + tg;
                unsigned a0 = As[ar    ][kk + tr];
                unsigned a1 = As[ar + 8][kk + tr];
                unsigned a2 = As[ar    ][kk + tr + 4];
                unsigned a3 = As[ar + 8][kk + tr + 4];
#pragma unroll
                for (int nt = 0; nt < 4; nt++)
                    mma_tf32(acc[mt][nt], a0, a1, a2, a3, bf[nt][0], bf[nt][1]);
            }
        }
        __syncthreads();
    }

#pragma unroll
    for (int mt = 0; mt < 4; mt++) {
#pragma unroll
        for (int nt = 0; nt < 4; nt++) {
            const int cg = wn + nt*8 + 2*tr;
            const float bb0 = bh[cg], bb1 = bh[cg + 1];
            const int r0g = row0 + wm + mt*16 + tg;
            const int r1g = r0g + 8;
            if (r0g < N) {
                __half2 h = __floats2half2_rn(acc[mt][nt][0] + bb0,
                                              acc[mt][nt][1] + bb1);
                *(__half2*)(out + (size_t)r0g * D + cg) = h;
            }
            if (r1g < N) {
                __half2 h = __floats2half2_rn(acc[mt][nt][2] + bb0,
                                              acc[mt][nt][3] + bb1);
                *(__half2*)(out + (size_t)r1g * D + cg) = h;
            }
        }
    }
}

// ---------------------------------------------------------------------------
// Edge pass: 16 lanes/edge, 2 edges/warp, 2 batched iterations (4 edges/warp,
// 32 edges/block). All 8 gather LDG.64s issued before any consumption ->
// MLP 8 per thread to cover random L2-hit latency.
// ---------------------------------------------------------------------------
__global__ __launch_bounds__(256) void edge_kernel(
    const void* __restrict__ srcp, const void* __restrict__ dstp,
    const float* __restrict__ W_out, const float* __restrict__ b_out,
    float* __restrict__ score, float* __restrict__ embs,
    long long E, int N)
{
    __shared__ float4 ws[64];
    __shared__ float2 sc[32];

    const int tid = threadIdx.x;
    if (tid < 64) ws[tid] = ((const float4*)W_out)[tid];
    __syncthreads();

    const int warp = tid >> 5;
    const int lane = tid & 31;
    const int sub  = lane >> 4;
    const int sl   = lane & 15;
    const long long e0 = (long long)blockIdx.x * 32 + warp * 4 + sub;
    const long long e1 = e0 + 2;

    const __half* __restrict__ hs = g_h[0];
    const __half* __restrict__ hd = g_h[1];
    const bool i64 = (g_idx64 != 0);

    // --- Load & clamp indices for both iterations ---
    int s0 = 0, d0i = 0, s1 = 0, d1i = 0;
    const bool v0 = (e0 < E), v1 = (e1 < E);
    if (v0) {
        s0  = i64 ? (int)((const long long*)srcp)[e0] : ((const int*)srcp)[e0];
        d0i = i64 ? (int)((const long long*)dstp)[e0] : ((const int*)dstp)[e0];
    }
    if (v1) {
        s1  = i64 ? (int)((const long long*)srcp)[e1] : ((const int*)srcp)[e1];
        d1i = i64 ? (int)((const long long*)dstp)[e1] : ((const int*)dstp)[e1];
    }
    s0  = min(max(s0, 0), N - 1);  d0i = min(max(d0i, 0), N - 1);
    s1  = min(max(s1, 0), N - 1);  d1i = min(max(d1i, 0), N - 1);

    // --- Issue all 8 gathers (independent) ---
    const __half* rs0 = hs + (size_t)s0  * D;
    const __half* rd0 = hd + (size_t)d0i * D;
    const __half* rs1 = hs + (size_t)s1  * D;
    const __half* rd1 = hd + (size_t)d1i * D;

    uint2 a0lo = ((const uint2*)rs0)[sl];
    uint2 a0hi = ((const uint2*)(rs0 + 64))[sl];
    uint2 b0lo = ((const uint2*)rd0)[sl];
    uint2 b0hi = ((const uint2*)(rd0 + 64))[sl];
    uint2 a1lo = ((const uint2*)rs1)[sl];
    uint2 a1hi = ((const uint2*)(rs1 + 64))[sl];
    uint2 b1lo = ((const uint2*)rd1)[sl];
    uint2 b1hi = ((const uint2*)(rd1 + 64))[sl];

    const float4 wa_lo = ws[sl];
    const float4 wa_hi = ws[16 + sl];
    const float4 wb_lo = ws[32 + sl];
    const float4 wb_hi = ws[48 + sl];
    const __half2 z = __float2half2_rn(0.0f);

#pragma unroll
    for (int it = 0; it < 2; it++) {
        const long long e = it ? e1 : e0;
        if (it ? !v1 : !v0) continue;
        const uint2 alo = it ? a1lo : a0lo;
        const uint2 ahi = it ? a1hi : a0hi;
        const uint2 blo = it ? b1lo : b0lo;
        const uint2 bhi = it ? b1hi : b0hi;

        __half2 l0 = __hmax2(__hadd2(*(const __half2*)&alo.x, *(const __half2*)&blo.x), z);
        __half2 l1 = __hmax2(__hadd2(*(const __half2*)&alo.y, *(const __half2*)&blo.y), z);
        __half2 h0 = __hmax2(__hadd2(*(const __half2*)&ahi.x, *(const __half2*)&bhi.x), z);
        __half2 h1 = __hmax2(__hadd2(*(const __half2*)&ahi.y, *(const __half2*)&bhi.y), z);

        float2 fl0 = __half22float2(l0);
        float2 fl1 = __half22float2(l1);
        float2 fh0 = __half22float2(h0);
        float2 fh1 = __half22float2(h1);

        float* ep = embs + (size_t)e * D;
        *(float4*)(ep + sl * 4)      = make_float4(fl0.x, fl0.y, fl1.x, fl1.y);
        *(float4*)(ep + 64 + sl * 4) = make_float4(fh0.x, fh0.y, fh1.x, fh1.y);

        float p0 = fl0.x*wa_lo.x + fl0.y*wa_lo.y + fl1.x*wa_lo.z + fl1.y*wa_lo.w
                 + fh0.x*wa_hi.x + fh0.y*wa_hi.y + fh1.x*wa_hi.z + fh1.y*wa_hi.w;
        float p1 = fl0.x*wb_lo.x + fl0.y*wb_lo.y + fl1.x*wb_lo.z + fl1.y*wb_lo.w
                 + fh0.x*wb_hi.x + fh0.y*wb_hi.y + fh1.x*wb_hi.z + fh1.y*wb_hi.w;

#pragma unroll
        for (int o = 8; o > 0; o >>= 1) {
            p0 += __shfl_xor_sync(0xffffffffu, p0, o);
            p1 += __shfl_xor_sync(0xffffffffu, p1, o);
        }
        if (sl == 0)
            sc[warp * 4 + it * 2 + sub] = make_float2(p0 + b_out[0], p1 + b_out[1]);
    }
    __syncthreads();

    const long long base = (long long)blockIdx.x * 32;
    if (tid < 32 && base + tid < E) {
        // sc slot mapping: warp w, iter it, sub -> w*4 + it*2 + sub holds edge
        // base + w*4 + it*2 + sub. tid enumerates exactly those slots.
        ((float2*)score)[base + tid] = sc[tid];
    }
}

extern "C" void kernel_launch(void* const* d_in, const int* in_sizes, int n_in,
                              void* d_out, int out_size)
{
    const float* x     = (const float*)d_in[0];
    const void*  src   = d_in[1];
    const void*  dst   = d_in[2];
    const float* W_src = (const float*)d_in[3];
    const float* b_src = (const float*)d_in[4];
    const float* W_dst = (const float*)d_in[5];
    const float* b_dst = (const float*)d_in[6];
    const float* W_out = (const float*)d_in[7];
    const float* b_out = (const float*)d_in[8];

    const int N = in_sizes[0] / D;
    const long long E = in_sizes[1];

    float* out   = (float*)d_out;
    float* score = out;                       // [E, 2]
    float* embs  = out + (size_t)E * 2;       // [E, 128]

    const int gb = (N + 127) / 128;
    node_gemm_fused<<<gb, 512>>>(x, W_src, b_src, W_dst, b_dst,
                                 (const long long*)src, N);

    const int eb = (int)((E + 31) / 32);
    edge_kernel<<<eb, 256>>>(src, dst, W_out, b_out, score, embs, E, N);
}

// round 8
// speedup vs baseline: 1.2902x; 1.2902x over previous
#include <cuda_runtime.h>
#include <cuda_fp16.h>

#define D 128
#define NMAX 100000
#define PAD 20

__device__ __half g_h[2][(size_t)NMAX * D];
__device__ int g_idx64;

__device__ __forceinline__ unsigned f2tf32(float f) {
    unsigned u;
    asm("cvt.rna.tf32.f32 %0, %1;" : "=r"(u) : "f"(f));
    return u;
}

__device__ __forceinline__ void mma_tf32(float c[4], unsigned a0, unsigned a1,
                                         unsigned a2, unsigned a3,
                                         unsigned b0, unsigned b1) {
    asm volatile(
        "mma.sync.aligned.m16n8k8.row.col.f32.tf32.tf32.f32 "
        "{%0,%1,%2,%3},{%4,%5,%6,%7},{%8,%9},{%0,%1,%2,%3};"
        : "+f"(c[0]), "+f"(c[1]), "+f"(c[2]), "+f"(c[3])
        : "r"(a0), "r"(a1), "r"(a2), "r"(a3), "r"(b0), "r"(b1));
}

// ---------------------------------------------------------------------------
// Fused node GEMM: one pass over x computes BOTH h_src and h_dst.
// Warps 0-7 -> W_src, warps 8-15 -> W_dst. Inlined index-dtype probe.
// ---------------------------------------------------------------------------
__global__ __launch_bounds__(512, 1) void node_gemm_fused(
    const float* __restrict__ x,
    const float* __restrict__ Wsrc, const float* __restrict__ bsrc,
    const float* __restrict__ Wdst, const float* __restrict__ bdst,
    const long long* __restrict__ idxprobe, int N)
{
    __shared__ unsigned As[128][PAD];
    __shared__ unsigned Bs[2][128][PAD];

    const int tid  = threadIdx.x;

    if (blockIdx.x == 0 && tid == 0) {
        int ok = 0;
#pragma unroll
        for (int i = 0; i < 16; i++) {
            long long v = idxprobe[i];
            if (v >= 0 && v < (long long)N) ok++;
        }
        g_idx64 = (ok >= 12) ? 1 : 0;
    }

    const int wid  = tid >> 5;
    const int lane = tid & 31;
    const int half = wid >> 3;
    const int w    = wid & 7;
    const int wm   = (w >> 2) * 64;
    const int wn   = (w & 3) * 32;
    const int row0 = blockIdx.x * 128;
    const int tg   = lane >> 2;
    const int tr   = lane & 3;

    const float* __restrict__ bh = half ? bdst : bsrc;
    __half* __restrict__ out = g_h[half];

    float acc[4][4][4];
#pragma unroll
    for (int i = 0; i < 4; i++)
#pragma unroll
        for (int j = 0; j < 4; j++)
#pragma unroll
            for (int k = 0; k < 4; k++) acc[i][j][k] = 0.0f;

    const int lrow  = tid >> 2;
    const int lcol4 = (tid & 3) * 4;

    for (int kt = 0; kt < 128; kt += 16) {
        float4 av = make_float4(0.f, 0.f, 0.f, 0.f);
        if (row0 + lrow < N)
            av = *(const float4*)(x + (size_t)(row0 + lrow) * D + kt + lcol4);
        As[lrow][lcol4+0] = f2tf32(av.x); As[lrow][lcol4+1] = f2tf32(av.y);
        As[lrow][lcol4+2] = f2tf32(av.z); As[lrow][lcol4+3] = f2tf32(av.w);

        const float4 ws = *(const float4*)(Wsrc + (size_t)lrow * D + kt + lcol4);
        Bs[0][lrow][lcol4+0] = f2tf32(ws.x); Bs[0][lrow][lcol4+1] = f2tf32(ws.y);
        Bs[0][lrow][lcol4+2] = f2tf32(ws.z); Bs[0][lrow][lcol4+3] = f2tf32(ws.w);

        const float4 wd = *(const float4*)(Wdst + (size_t)lrow * D + kt + lcol4);
        Bs[1][lrow][lcol4+0] = f2tf32(wd.x); Bs[1][lrow][lcol4+1] = f2tf32(wd.y);
        Bs[1][lrow][lcol4+2] = f2tf32(wd.z); Bs[1][lrow][lcol4+3] = f2tf32(wd.w);
        __syncthreads();

#pragma unroll
        for (int kk = 0; kk < 16; kk += 8) {
            unsigned bf[4][2];
#pragma unroll
            for (int nt = 0; nt < 4; nt++) {
                bf[nt][0] = Bs[half][wn + nt*8 + tg][kk + tr];
                bf[nt][1] = Bs[half][wn + nt*8 + tg][kk + tr + 4];
            }
#pragma unroll
            for (int mt = 0; mt < 4; mt++) {
                const int ar = wm + mt*16 + tg;
                unsigned a0 = As[ar    ][kk + tr];
                unsigned a1 = As[ar + 8][kk + tr];
                unsigned a2 = As[ar    ][kk + tr + 4];
                unsigned a3 = As[ar + 8][kk + tr + 4];
#pragma unroll
                for (int nt = 0; nt < 4; nt++)
                    mma_tf32(acc[mt][nt], a0, a1, a2, a3, bf[nt][0], bf[nt][1]);
            }
        }
        __syncthreads();
    }

#pragma unroll
    for (int mt = 0; mt < 4; mt++) {
#pragma unroll
        for (int nt = 0; nt < 4; nt++) {
            const int cg = wn + nt*8 + 2*tr;
            const float bb0 = bh[cg], bb1 = bh[cg + 1];
            const int r0g = row0 + wm + mt*16 + tg;
            const int r1g = r0g + 8;
            if (r0g < N) {
                __half2 h = __floats2half2_rn(acc[mt][nt][0] + bb0,
                                              acc[mt][nt][1] + bb1);
                *(__half2*)(out + (size_t)r0g * D + cg) = h;
            }
            if (r1g < N) {
                __half2 h = __floats2half2_rn(acc[mt][nt][2] + bb0,
                                              acc[mt][nt][3] + bb1);
                *(__half2*)(out + (size_t)r1g * D + cg) = h;
            }
        }
    }
}

// ---------------------------------------------------------------------------
// Edge pass (round-6 shape: 32 regs, high occupancy): 16 lanes/edge,
// 2 edges/warp, 16 edges per 256-thread block. Lane sl owns cols
// [sl*4,+4) and [64+sl*4,+4): contiguous 256B stores per edge, LDG.64
// gathers covering one full 128B line per edge per instruction.
// ---------------------------------------------------------------------------
__global__ __launch_bounds__(256) void edge_kernel(
    const void* __restrict__ srcp, const void* __restrict__ dstp,
    const float* __restrict__ W_out, const float* __restrict__ b_out,
    float* __restrict__ score, float* __restrict__ embs,
    long long E, int N)
{
    __shared__ float4 ws[64];
    __shared__ float2 sc[16];

    const int tid = threadIdx.x;
    if (tid < 64) ws[tid] = ((const float4*)W_out)[tid];
    __syncthreads();

    const int warp = tid >> 5;
    const int lane = tid & 31;
    const int sub  = lane >> 4;
    const int sl   = lane & 15;
    const long long e = (long long)blockIdx.x * 16 + warp * 2 + sub;

    const __half* __restrict__ hs = g_h[0];
    const __half* __restrict__ hd = g_h[1];

    if (e < E) {
        int s, d;
        if (g_idx64) {
            s = (int)((const long long*)srcp)[e];
            d = (int)((const long long*)dstp)[e];
        } else {
            s = ((const int*)srcp)[e];
            d = ((const int*)dstp)[e];
        }
        s = min(max(s, 0), N - 1);
        d = min(max(d, 0), N - 1);

        const __half* rs = hs + (size_t)s * D;
        const __half* rd = hd + (size_t)d * D;

        const uint2 sa_lo = ((const uint2*)rs)[sl];
        const uint2 sa_hi = ((const uint2*)(rs + 64))[sl];
        const uint2 da_lo = ((const uint2*)rd)[sl];
        const uint2 da_hi = ((const uint2*)(rd + 64))[sl];

        const __half2 z = __float2half2_rn(0.0f);
        __half2 l0 = __hmax2(__hadd2(*(const __half2*)&sa_lo.x, *(const __half2*)&da_lo.x), z);
        __half2 l1 = __hmax2(__hadd2(*(const __half2*)&sa_lo.y, *(const __half2*)&da_lo.y), z);
        __half2 h0 = __hmax2(__hadd2(*(const __half2*)&sa_hi.x, *(const __half2*)&da_hi.x), z);
        __half2 h1 = __hmax2(__hadd2(*(const __half2*)&sa_hi.y, *(const __half2*)&da_hi.y), z);

        float2 fl0 = __half22float2(l0);
        float2 fl1 = __half22float2(l1);
        float2 fh0 = __half22float2(h0);
        float2 fh1 = __half22float2(h1);

        float* ep = embs + (size_t)e * D;
        *(float4*)(ep + sl * 4)      = make_float4(fl0.x, fl0.y, fl1.x, fl1.y);
        *(float4*)(ep + 64 + sl * 4) = make_float4(fh0.x, fh0.y, fh1.x, fh1.y);

        const float4 wa_lo = ws[sl];
        const float4 wa_hi = ws[16 + sl];
        const float4 wb_lo = ws[32 + sl];
        const float4 wb_hi = ws[48 + sl];

        float d0 = fl0.x*wa_lo.x + fl0.y*wa_lo.y + fl1.x*wa_lo.z + fl1.y*wa_lo.w
                 + fh0.x*wa_hi.x + fh0.y*wa_hi.y + fh1.x*wa_hi.z + fh1.y*wa_hi.w;
        float d1 = fl0.x*wb_lo.x + fl0.y*wb_lo.y + fl1.x*wb_lo.z + fl1.y*wb_lo.w
                 + fh0.x*wb_hi.x + fh0.y*wb_hi.y + fh1.x*wb_hi.z + fh1.y*wb_hi.w;

#pragma unroll
        for (int o = 8; o > 0; o >>= 1) {
            d0 += __shfl_xor_sync(0xffffffffu, d0, o);
            d1 += __shfl_xor_sync(0xffffffffu, d1, o);
        }
        if (sl == 0)
            sc[warp * 2 + sub] = make_float2(d0 + b_out[0], d1 + b_out[1]);
    }
    __syncthreads();

    const long long base = (long long)blockIdx.x * 16;
    if (tid < 16 && base + tid < E)
        ((float2*)score)[base + tid] = sc[tid];
}

extern "C" void kernel_launch(void* const* d_in, const int* in_sizes, int n_in,
                              void* d_out, int out_size)
{
    const float* x     = (const float*)d_in[0];
    const void*  src   = d_in[1];
    const void*  dst   = d_in[2];
    const float* W_src = (const float*)d_in[3];
    const float* b_src = (const float*)d_in[4];
    const float* W_dst = (const float*)d_in[5];
    const float* b_dst = (const float*)d_in[6];
    const float* W_out = (const float*)d_in[7];
    const float* b_out = (const float*)d_in[8];

    const int N = in_sizes[0] / D;
    const long long E = in_sizes[1];

    float* out   = (float*)d_out;
    float* score = out;                       // [E, 2]
    float* embs  = out + (size_t)E * 2;       // [E, 128]

    const int gb = (N + 127) / 128;
    node_gemm_fused<<<gb, 512>>>(x, W_src, b_src, W_dst, b_dst,
                                 (const long long*)src, N);

    const int eb = (int)((E + 15) / 16);
    edge_kernel<<<eb, 256>>>(src, dst, W_out, b_out, score, embs, E, N);
}

// round 10
// speedup vs baseline: 1.3584x; 1.0529x over previous
#include <cuda_runtime.h>
#include <cuda_fp16.h>

#define D 128
#define NMAX 100000
#define PAD 20

__device__ __half g_h[2][(size_t)NMAX * D];
__device__ int g_idx64;

__device__ __forceinline__ unsigned f2tf32(float f) {
    unsigned u;
    asm("cvt.rna.tf32.f32 %0, %1;" : "=r"(u) : "f"(f));
    return u;
}

__device__ __forceinline__ void mma_tf32(float c[4], unsigned a0, unsigned a1,
                                         unsigned a2, unsigned a3,
                                         unsigned b0, unsigned b1) {
    asm volatile(
        "mma.sync.aligned.m16n8k8.row.col.f32.tf32.tf32.f32 "
        "{%0,%1,%2,%3},{%4,%5,%6,%7},{%8,%9},{%0,%1,%2,%3};"
        : "+f"(c[0]), "+f"(c[1]), "+f"(c[2]), "+f"(c[3])
        : "r"(a0), "r"(a1), "r"(a2), "r"(a3), "r"(b0), "r"(b1));
}

// L2 evict_last gather via createpolicy + cache_hint (legal at any width,
// unlike the inline .L2::evict_last qualifier which needs 256-bit loads).
__device__ __forceinline__ uint2 ldg_el(const void* p, unsigned long long pol) {
    uint2 r;
    asm volatile("ld.global.nc.L2::cache_hint.v2.u32 {%0,%1}, [%2], %3;"
                 : "=r"(r.x), "=r"(r.y) : "l"(p), "l"(pol));
    return r;
}

// ---------------------------------------------------------------------------
// Fused node GEMM, software-pipelined: next K-tile loaded to registers while
// current tile computes from smem. Warps 0-7 -> W_src, 8-15 -> W_dst.
// ---------------------------------------------------------------------------
__global__ __launch_bounds__(512, 1) void node_gemm_fused(
    const float* __restrict__ x,
    const float* __restrict__ Wsrc, const float* __restrict__ bsrc,
    const float* __restrict__ Wdst, const float* __restrict__ bdst,
    const long long* __restrict__ idxprobe, int N)
{
    __shared__ unsigned As[128][PAD];
    __shared__ unsigned Bs[2][128][PAD];

    const int tid  = threadIdx.x;

    if (blockIdx.x == 0 && tid == 0) {
        int ok = 0;
#pragma unroll
        for (int i = 0; i < 16; i++) {
            long long v = idxprobe[i];
            if (v >= 0 && v < (long long)N) ok++;
        }
        g_idx64 = (ok >= 12) ? 1 : 0;
    }

    const int wid  = tid >> 5;
    const int lane = tid & 31;
    const int half = wid >> 3;
    const int w    = wid & 7;
    const int wm   = (w >> 2) * 64;
    const int wn   = (w & 3) * 32;
    const int row0 = blockIdx.x * 128;
    const int tg   = lane >> 2;
    const int tr   = lane & 3;

    const float* __restrict__ bh = half ? bdst : bsrc;
    __half* __restrict__ out = g_h[half];

    float acc[4][4][4];
#pragma unroll
    for (int i = 0; i < 4; i++)
#pragma unroll
        for (int j = 0; j < 4; j++)
#pragma unroll
            for (int k = 0; k < 4; k++) acc[i][j][k] = 0.0f;

    const int lrow  = tid >> 2;
    const int lcol4 = (tid & 3) * 4;
    const bool rowok = (row0 + lrow < N);
    const float* xrow = x    + (size_t)(row0 + lrow) * D + lcol4;
    const float* wsr  = Wsrc + (size_t)lrow * D + lcol4;
    const float* wdr  = Wdst + (size_t)lrow * D + lcol4;

    float4 av = make_float4(0.f, 0.f, 0.f, 0.f);
    if (rowok) av = *(const float4*)xrow;
    float4 wsv = *(const float4*)wsr;
    float4 wdv = *(const float4*)wdr;

#pragma unroll
    for (int it = 0; it < 8; it++) {
        As[lrow][lcol4+0] = f2tf32(av.x); As[lrow][lcol4+1] = f2tf32(av.y);
        As[lrow][lcol4+2] = f2tf32(av.z); As[lrow][lcol4+3] = f2tf32(av.w);
        Bs[0][lrow][lcol4+0] = f2tf32(wsv.x); Bs[0][lrow][lcol4+1] = f2tf32(wsv.y);
        Bs[0][lrow][lcol4+2] = f2tf32(wsv.z); Bs[0][lrow][lcol4+3] = f2tf32(wsv.w);
        Bs[1][lrow][lcol4+0] = f2tf32(wdv.x); Bs[1][lrow][lcol4+1] = f2tf32(wdv.y);
        Bs[1][lrow][lcol4+2] = f2tf32(wdv.z); Bs[1][lrow][lcol4+3] = f2tf32(wdv.w);
        __syncthreads();

        if (it < 7) {
            const int off = (it + 1) * 16;
            av = make_float4(0.f, 0.f, 0.f, 0.f);
            if (rowok) av = *(const float4*)(xrow + off);
            wsv = *(const float4*)(wsr + off);
            wdv = *(const float4*)(wdr + off);
        }

#pragma unroll
        for (int kk = 0; kk < 16; kk += 8) {
            unsigned bf[4][2];
#pragma unroll
            for (int nt = 0; nt < 4; nt++) {
                bf[nt][0] = Bs[half][wn + nt*8 + tg][kk + tr];
                bf[nt][1] = Bs[half][wn + nt*8 + tg][kk + tr + 4];
            }
#pragma unroll
            for (int mt = 0; mt < 4; mt++) {
                const int ar = wm + mt*16 + tg;
                unsigned a0 = As[ar    ][kk + tr];
                unsigned a1 = As[ar + 8][kk + tr];
                unsigned a2 = As[ar    ][kk + tr + 4];
                unsigned a3 = As[ar + 8][kk + tr + 4];
#pragma unroll
                for (int nt = 0; nt < 4; nt++)
                    mma_tf32(acc[mt][nt], a0, a1, a2, a3, bf[nt][0], bf[nt][1]);
            }
        }
        __syncthreads();
    }

#pragma unroll
    for (int mt = 0; mt < 4; mt++) {
#pragma unroll
        for (int nt = 0; nt < 4; nt++) {
            const int cg = wn + nt*8 + 2*tr;
            const float bb0 = bh[cg], bb1 = bh[cg + 1];
            const int r0g = row0 + wm + mt*16 + tg;
            const int r1g = r0g + 8;
            if (r0g < N) {
                __half2 h = __floats2half2_rn(acc[mt][nt][0] + bb0,
                                              acc[mt][nt][1] + bb1);
                *(__half2*)(out + (size_t)r0g * D + cg) = h;
            }
            if (r1g < N) {
                __half2 h = __floats2half2_rn(acc[mt][nt][2] + bb0,
                                              acc[mt][nt][3] + bb1);
                *(__half2*)(out + (size_t)r1g * D + cg) = h;
            }
        }
    }
}

// ---------------------------------------------------------------------------
// Edge pass: 16 lanes/edge, 2 edges/warp. Gathers carry an evict_last L2
// policy so the 51MB h arrays stay resident against the output write stream.
// ---------------------------------------------------------------------------
__global__ __launch_bounds__(256) void edge_kernel(
    const void* __restrict__ srcp, const void* __restrict__ dstp,
    const float* __restrict__ W_out, const float* __restrict__ b_out,
    float* __restrict__ score, float* __restrict__ embs,
    long long E, int N)
{
    __shared__ float4 ws[64];
    __shared__ float2 sc[16];

    const int tid = threadIdx.x;
    if (tid < 64) ws[tid] = ((const float4*)W_out)[tid];
    __syncthreads();

    unsigned long long pol;
    asm("createpolicy.fractional.L2::evict_last.b64 %0, 1.0;" : "=l"(pol));

    const int warp = tid >> 5;
    const int lane = tid & 31;
    const int sub  = lane >> 4;
    const int sl   = lane & 15;
    const long long e = (long long)blockIdx.x * 16 + warp * 2 + sub;

    const __half* __restrict__ hs = g_h[0];
    const __half* __restrict__ hd = g_h[1];

    if (e < E) {
        int s, d;
        if (g_idx64) {
            s = (int)((const long long*)srcp)[e];
            d = (int)((const long long*)dstp)[e];
        } else {
            s = ((const int*)srcp)[e];
            d = ((const int*)dstp)[e];
        }
        s = min(max(s, 0), N - 1);
        d = min(max(d, 0), N - 1);

        const __half* rs = hs + (size_t)s * D;
        const __half* rd = hd + (size_t)d * D;

        const uint2 sa_lo = ldg_el((const uint2*)rs + sl, pol);
        const uint2 sa_hi = ldg_el((const uint2*)(rs + 64) + sl, pol);
        const uint2 da_lo = ldg_el((const uint2*)rd + sl, pol);
        const uint2 da_hi = ldg_el((const uint2*)(rd + 64) + sl, pol);

        const __half2 z = __float2half2_rn(0.0f);
        __half2 l0 = __hmax2(__hadd2(*(const __half2*)&sa_lo.x, *(const __half2*)&da_lo.x), z);
        __half2 l1 = __hmax2(__hadd2(*(const __half2*)&sa_lo.y, *(const __half2*)&da_lo.y), z);
        __half2 h0 = __hmax2(__hadd2(*(const __half2*)&sa_hi.x, *(const __half2*)&da_hi.x), z);
        __half2 h1 = __hmax2(__hadd2(*(const __half2*)&sa_hi.y, *(const __half2*)&da_hi.y), z);

        float2 fl0 = __half22float2(l0);
        float2 fl1 = __half22float2(l1);
        float2 fh0 = __half22float2(h0);
        float2 fh1 = __half22float2(h1);

        float* ep = embs + (size_t)e * D;
        *(float4*)(ep + sl * 4)      = make_float4(fl0.x, fl0.y, fl1.x, fl1.y);
        *(float4*)(ep + 64 + sl * 4) = make_float4(fh0.x, fh0.y, fh1.x, fh1.y);

        const float4 wa_lo = ws[sl];
        const float4 wa_hi = ws[16 + sl];
        const float4 wb_lo = ws[32 + sl];
        const float4 wb_hi = ws[48 + sl];

        float d0 = fl0.x*wa_lo.x + fl0.y*wa_lo.y + fl1.x*wa_lo.z + fl1.y*wa_lo.w
                 + fh0.x*wa_hi.x + fh0.y*wa_hi.y + fh1.x*wa_hi.z + fh1.y*wa_hi.w;
        float d1 = fl0.x*wb_lo.x + fl0.y*wb_lo.y + fl1.x*wb_lo.z + fl1.y*wb_lo.w
                 + fh0.x*wb_hi.x + fh0.y*wb_hi.y + fh1.x*wb_hi.z + fh1.y*wb_hi.w;

#pragma unroll
        for (int o = 8; o > 0; o >>= 1) {
            d0 += __shfl_xor_sync(0xffffffffu, d0, o);
            d1 += __shfl_xor_sync(0xffffffffu, d1, o);
        }
        if (sl == 0)
            sc[warp * 2 + sub] = make_float2(d0 + b_out[0], d1 + b_out[1]);
    }
    __syncthreads();

    const long long base = (long long)blockIdx.x * 16;
    if (tid < 16 && base + tid < E)
        ((float2*)score)[base + tid] = sc[tid];
}

extern "C" void kernel_launch(void* const* d_in, const int* in_sizes, int n_in,
                              void* d_out, int out_size)
{
    const float* x     = (const float*)d_in[0];
    const void*  src   = d_in[1];
    const void*  dst   = d_in[2];
    const float* W_src = (const float*)d_in[3];
    const float* b_src = (const float*)d_in[4];
    const float* W_dst = (const float*)d_in[5];
    const float* b_dst = (const float*)d_in[6];
    const float* W_out = (const float*)d_in[7];
    const float* b_out = (const float*)d_in[8];

    const int N = in_sizes[0] / D;
    const long long E = in_sizes[1];

    float* out   = (float*)d_out;
    float* score = out;                       // [E, 2]
    float* embs  = out + (size_t)E * 2;       // [E, 128]

    const int gb = (N + 127) / 128;
    node_gemm_fused<<<gb, 512>>>(x, W_src, b_src, W_dst, b_dst,
                                 (const long long*)src, N);

    const int eb = (int)((E + 15) / 16);
    edge_kernel<<<eb, 256>>>(src, dst, W_out, b_out, score, embs, E, N);
}

// round 11
// speedup vs baseline: 1.3587x; 1.0002x over previous
#include <cuda_runtime.h>
#include <cuda_fp16.h>

#define D 128
#define NMAX 100000
#define PAD 20

__device__ __half g_h[2][(size_t)NMAX * D];
__device__ int g_idx64;

__device__ __forceinline__ unsigned f2tf32(float f) {
    unsigned u;
    asm("cvt.rna.tf32.f32 %0, %1;" : "=r"(u) : "f"(f));
    return u;
}

__device__ __forceinline__ void mma_tf32(float c[4], unsigned a0, unsigned a1,
                                         unsigned a2, unsigned a3,
                                         unsigned b0, unsigned b1) {
    asm volatile(
        "mma.sync.aligned.m16n8k8.row.col.f32.tf32.tf32.f32 "
        "{%0,%1,%2,%3},{%4,%5,%6,%7},{%8,%9},{%0,%1,%2,%3};"
        : "+f"(c[0]), "+f"(c[1]), "+f"(c[2]), "+f"(c[3])
        : "r"(a0), "r"(a1), "r"(a2), "r"(a3), "r"(b0), "r"(b1));
}

// evict_last gather (keep h resident).
__device__ __forceinline__ uint2 ldg_el(const void* p, unsigned long long pol) {
    uint2 r;
    asm volatile("ld.global.nc.L2::cache_hint.v2.u32 {%0,%1}, [%2], %3;"
                 : "=r"(r.x), "=r"(r.y) : "l"(p), "l"(pol));
    return r;
}

// evict_first streaming store (keep the 832MB write stream out of L2's way).
__device__ __forceinline__ void stg_ef(void* p, float4 v, unsigned long long pol) {
    asm volatile("st.global.L2::cache_hint.v4.f32 [%0], {%1,%2,%3,%4}, %5;"
                 :: "l"(p), "f"(v.x), "f"(v.y), "f"(v.z), "f"(v.w), "l"(pol)
                 : "memory");
}

// ---------------------------------------------------------------------------
// Node GEMM, one half (src or dst) per block via blockIdx.y.
// 256 threads, 8 warps, 128x128 tile, register-pipelined K loop.
// 2 blocks/SM co-resident -> sync/load stalls overlap across blocks.
// ---------------------------------------------------------------------------
__global__ __launch_bounds__(256, 2) void node_gemm_half(
    const float* __restrict__ x,
    const float* __restrict__ Wsrc, const float* __restrict__ bsrc,
    const float* __restrict__ Wdst, const float* __restrict__ bdst,
    const long long* __restrict__ idxprobe, int N)
{
    __shared__ unsigned As[128][PAD];
    __shared__ unsigned Bs[128][PAD];

    const int tid  = threadIdx.x;
    const int half = blockIdx.y;

    if (blockIdx.x == 0 && half == 0 && tid == 0) {
        int ok = 0;
#pragma unroll
        for (int i = 0; i < 16; i++) {
            long long v = idxprobe[i];
            if (v >= 0 && v < (long long)N) ok++;
        }
        g_idx64 = (ok >= 12) ? 1 : 0;
    }

    const float* __restrict__ W  = half ? Wdst : Wsrc;
    const float* __restrict__ bh = half ? bdst : bsrc;
    __half* __restrict__ out = g_h[half];

    const int wid  = tid >> 5;
    const int lane = tid & 31;
    const int wm   = (wid >> 2) * 64;
    const int wn   = (wid & 3) * 32;
    const int row0 = blockIdx.x * 128;
    const int tg   = lane >> 2;
    const int tr   = lane & 3;

    float acc[4][4][4];
#pragma unroll
    for (int i = 0; i < 4; i++)
#pragma unroll
        for (int j = 0; j < 4; j++)
#pragma unroll
            for (int k = 0; k < 4; k++) acc[i][j][k] = 0.0f;

    const int lrow = tid >> 1;            // 0..127
    const int lcol = (tid & 1) * 8;       // 0 or 8
    const bool rowok = (row0 + lrow < N);
    const float* xrow = x + (size_t)(row0 + lrow) * D + lcol;
    const float* wr   = W + (size_t)lrow * D + lcol;

    // Prologue: tile 0 into registers.
    float4 a0v = make_float4(0.f,0.f,0.f,0.f), a1v = a0v;
    if (rowok) { a0v = *(const float4*)xrow; a1v = *(const float4*)(xrow + 4); }
    float4 w0v = *(const float4*)wr;
    float4 w1v = *(const float4*)(wr + 4);

#pragma unroll
    for (int it = 0; it < 8; it++) {
        As[lrow][lcol+0] = f2tf32(a0v.x); As[lrow][lcol+1] = f2tf32(a0v.y);
        As[lrow][lcol+2] = f2tf32(a0v.z); As[lrow][lcol+3] = f2tf32(a0v.w);
        As[lrow][lcol+4] = f2tf32(a1v.x); As[lrow][lcol+5] = f2tf32(a1v.y);
        As[lrow][lcol+6] = f2tf32(a1v.z); As[lrow][lcol+7] = f2tf32(a1v.w);
        Bs[lrow][lcol+0] = f2tf32(w0v.x); Bs[lrow][lcol+1] = f2tf32(w0v.y);
        Bs[lrow][lcol+2] = f2tf32(w0v.z); Bs[lrow][lcol+3] = f2tf32(w0v.w);
        Bs[lrow][lcol+4] = f2tf32(w1v.x); Bs[lrow][lcol+5] = f2tf32(w1v.y);
        Bs[lrow][lcol+6] = f2tf32(w1v.z); Bs[lrow][lcol+7] = f2tf32(w1v.w);
        __syncthreads();

        if (it < 7) {
            const int off = (it + 1) * 16;
            a0v = make_float4(0.f,0.f,0.f,0.f); a1v = a0v;
            if (rowok) {
                a0v = *(const float4*)(xrow + off);
                a1v = *(const float4*)(xrow + off + 4);
            }
            w0v = *(const float4*)(wr + off);
            w1v = *(const float4*)(wr + off + 4);
        }

#pragma unroll
        for (int kk = 0; kk < 16; kk += 8) {
            unsigned bf[4][2];
#pragma unroll
            for (int nt = 0; nt < 4; nt++) {
                bf[nt][0] = Bs[wn + nt*8 + tg][kk + tr];
                bf[nt][1] = Bs[wn + nt*8 + tg][kk + tr + 4];
            }
#pragma unroll
            for (int mt = 0; mt < 4; mt++) {
                const int ar = wm + mt*16 + tg;
                unsigned q0 = As[ar    ][kk + tr];
                unsigned q1 = As[ar + 8][kk + tr];
                unsigned q2 = As[ar    ][kk + tr + 4];
                unsigned q3 = As[ar + 8][kk + tr + 4];
#pragma unroll
                for (int nt = 0; nt < 4; nt++)
                    mma_tf32(acc[mt][nt], q0, q1, q2, q3, bf[nt][0], bf[nt][1]);
            }
        }
        __syncthreads();
    }

#pragma unroll
    for (int mt = 0; mt < 4; mt++) {
#pragma unroll
        for (int nt = 0; nt < 4; nt++) {
            const int cg = wn + nt*8 + 2*tr;
            const float bb0 = bh[cg], bb1 = bh[cg + 1];
            const int r0g = row0 + wm + mt*16 + tg;
            const int r1g = r0g + 8;
            if (r0g < N) {
                __half2 h = __floats2half2_rn(acc[mt][nt][0] + bb0,
                                              acc[mt][nt][1] + bb1);
                *(__half2*)(out + (size_t)r0g * D + cg) = h;
            }
            if (r1g < N) {
                __half2 h = __floats2half2_rn(acc[mt][nt][2] + bb0,
                                              acc[mt][nt][3] + bb1);
                *(__half2*)(out + (size_t)r1g * D + cg) = h;
            }
        }
    }
}

// ---------------------------------------------------------------------------
// Edge pass: 16 lanes/edge, 2 edges/warp. evict_last gathers + evict_first
// streaming stores: the write stream no longer evicts the 51MB h arrays.
// ---------------------------------------------------------------------------
__global__ __launch_bounds__(256) void edge_kernel(
    const void* __restrict__ srcp, const void* __restrict__ dstp,
    const float* __restrict__ W_out, const float* __restrict__ b_out,
    float* __restrict__ score, float* __restrict__ embs,
    long long E, int N)
{
    __shared__ float4 ws[64];
    __shared__ float2 sc[16];

    const int tid = threadIdx.x;
    if (tid < 64) ws[tid] = ((const float4*)W_out)[tid];
    __syncthreads();

    unsigned long long pol_l, pol_s;
    asm("createpolicy.fractional.L2::evict_last.b64 %0, 1.0;"  : "=l"(pol_l));
    asm("createpolicy.fractional.L2::evict_first.b64 %0, 1.0;" : "=l"(pol_s));

    const int warp = tid >> 5;
    const int lane = tid & 31;
    const int sub  = lane >> 4;
    const int sl   = lane & 15;
    const long long e = (long long)blockIdx.x * 16 + warp * 2 + sub;

    const __half* __restrict__ hs = g_h[0];
    const __half* __restrict__ hd = g_h[1];

    if (e < E) {
        int s, d;
        if (g_idx64) {
            s = (int)((const long long*)srcp)[e];
            d = (int)((const long long*)dstp)[e];
        } else {
            s = ((const int*)srcp)[e];
            d = ((const int*)dstp)[e];
        }
        s = min(max(s, 0), N - 1);
        d = min(max(d, 0), N - 1);

        const __half* rs = hs + (size_t)s * D;
        const __half* rd = hd + (size_t)d * D;

        const uint2 sa_lo = ldg_el((const uint2*)rs + sl, pol_l);
        const uint2 sa_hi = ldg_el((const uint2*)(rs + 64) + sl, pol_l);
        const uint2 da_lo = ldg_el((const uint2*)rd + sl, pol_l);
        const uint2 da_hi = ldg_el((const uint2*)(rd + 64) + sl, pol_l);

        const __half2 z = __float2half2_rn(0.0f);
        __half2 l0 = __hmax2(__hadd2(*(const __half2*)&sa_lo.x, *(const __half2*)&da_lo.x), z);
        __half2 l1 = __hmax2(__hadd2(*(const __half2*)&sa_lo.y, *(const __half2*)&da_lo.y), z);
        __half2 h0 = __hmax2(__hadd2(*(const __half2*)&sa_hi.x, *(const __half2*)&da_hi.x), z);
        __half2 h1 = __hmax2(__hadd2(*(const __half2*)&sa_hi.y, *(const __half2*)&da_hi.y), z);

        float2 fl0 = __half22float2(l0);
        float2 fl1 = __half22float2(l1);
        float2 fh0 = __half22float2(h0);
        float2 fh1 = __half22float2(h1);

        float* ep = embs + (size_t)e * D;
        stg_ef(ep + sl * 4,      make_float4(fl0.x, fl0.y, fl1.x, fl1.y), pol_s);
        stg_ef(ep + 64 + sl * 4, make_float4(fh0.x, fh0.y, fh1.x, fh1.y), pol_s);

        const float4 wa_lo = ws[sl];
        const float4 wa_hi = ws[16 + sl];
        const float4 wb_lo = ws[32 + sl];
        const float4 wb_hi = ws[48 + sl];

        float d0 = fl0.x*wa_lo.x + fl0.y*wa_lo.y + fl1.x*wa_lo.z + fl1.y*wa_lo.w
                 + fh0.x*wa_hi.x + fh0.y*wa_hi.y + fh1.x*wa_hi.z + fh1.y*wa_hi.w;
        float d1 = fl0.x*wb_lo.x + fl0.y*wb_lo.y + fl1.x*wb_lo.z + fl1.y*wb_lo.w
                 + fh0.x*wb_hi.x + fh0.y*wb_hi.y + fh1.x*wb_hi.z + fh1.y*wb_hi.w;

#pragma unroll
        for (int o = 8; o > 0; o >>= 1) {
            d0 += __shfl_xor_sync(0xffffffffu, d0, o);
            d1 += __shfl_xor_sync(0xffffffffu, d1, o);
        }
        if (sl == 0)
            sc[warp * 2 + sub] = make_float2(d0 + b_out[0], d1 + b_out[1]);
    }
    __syncthreads();

    const long long base = (long long)blockIdx.x * 16;
    if (tid < 16 && base + tid < E)
        ((float2*)score)[base + tid] = sc[tid];
}

extern "C" void kernel_launch(void* const* d_in, const int* in_sizes, int n_in,
                              void* d_out, int out_size)
{
    const float* x     = (const float*)d_in[0];
    const void*  src   = d_in[1];
    const void*  dst   = d_in[2];
    const float* W_src = (const float*)d_in[3];
    const float* b_src = (const float*)d_in[4];
    const float* W_dst = (const float*)d_in[5];
    const float* b_dst = (const float*)d_in[6];
    const float* W_out = (const float*)d_in[7];
    const float* b_out = (const float*)d_in[8];

    const int N = in_sizes[0] / D;
    const long long E = in_sizes[1];

    float* out   = (float*)d_out;
    float* score = out;                       // [E, 2]
    float* embs  = out + (size_t)E * 2;       // [E, 128]

    dim3 gg((N + 127) / 128, 2);
    node_gemm_half<<<gg, 256>>>(x, W_src, b_src, W_dst, b_dst,
                                (const long long*)src, N);

    const int eb = (int)((E + 15) / 16);
    edge_kernel<<<eb, 256>>>(src, dst, W_out, b_out, score, embs, E, N);
}